// round 13
// baseline (speedup 1.0000x reference)
#include <cuda_runtime.h>
#include <cstdint>

#define Bn 16
#define IMG (512*512)           // 2^18
#define NPX (Bn*IMG)            // 4194304
#define RS 128                  // region size
#define RPI 16                  // 4x4 regions per image
#define NREG (Bn*RPI)           // 256
#define THREADS 1024
#define NSUB 32                 // 8x4 subtiles of 16x32
#define ST 131                  // smem row stride (gcd(131,32)=1)
#define MS_WORDS (130*ST)
#define KS_WORDS (128*ST)
#define SMEM_BYTES ((MS_WORDS + KS_WORDS)*4)   // ~135 KB
#define MAX_CYCLES 64
#define MAX_PASSES 400
#define NFLAGS 2048

// ---- device globals (static scratch) ----
__device__ float g_bufA[NPX];          // xh
__device__ float g_bufB[NPX];          // rec2 -> Rmax
__device__ float g_bufC[NPX];          // M -> R
__device__ int   g_reg_epoch[NREG];
__device__ int   g_reg_trunc[NREG];
__device__ int   g_flag_arr[NFLAGS];
__device__ unsigned g_cc[Bn];
__device__ int g_hasone, g_haszero;
__device__ unsigned g_bar_count = 0;
__device__ volatile unsigned g_bar_gen = 0;

// ---- software grid barrier (all blocks resident: 1 block/SM via smem) ----
__device__ __forceinline__ void grid_sync(int nb) {
    __syncthreads();
    if (threadIdx.x == 0) {
        __threadfence();
        unsigned gen = g_bar_gen;
        unsigned t = atomicAdd(&g_bar_count, 1u);
        if (t == (unsigned)nb - 1u) {
            atomicExch(&g_bar_count, 0u);
            __threadfence();
            g_bar_gen = gen + 1u;
        } else {
            while (g_bar_gen == gen) { __nanosleep(64); }
        }
        __threadfence();
    }
    __syncthreads();
}

__device__ __forceinline__ float f3max(float a, float b, float c) {
    return fmaxf(fmaxf(a, b), c);
}

// ---- directional band sweeps of a 16x32 subtile (R10 chains, split) ----
// Return PER-LANE changed flag; caller warp-reduces with __any_sync.

__device__ int relax_down(float* MS, const float* KS, int wy, int wx, int lane) {
    int ch = 0;
    const unsigned F = 0xffffffffu;
    const int r0 = (wy << 4) + 1, c0 = (wx << 5) + 1;
    float haloL = 0.0f, haloR = 0.0f;
    if (lane < 18) {
        haloL = MS[(r0 - 1 + lane) * ST + (c0 - 1)];
        haloR = MS[(r0 - 1 + lane) * ST + (c0 + 32)];
    }
    const int c = c0 + lane;
    float pc = MS[(r0 - 1) * ST + c];
    #pragma unroll 4
    for (int yy = 0; yy < 16; yy++) {
        float l  = __shfl_up_sync(F, pc, 1);
        float r  = __shfl_down_sync(F, pc, 1);
        float hl = __shfl_sync(F, haloL, yy);
        float hr = __shfl_sync(F, haloR, yy);
        if (lane == 0)  l = hl;
        if (lane == 31) r = hr;
        const int row = r0 + yy;
        float cur = MS[row * ST + c];
        float nv  = fminf(fmaxf(cur, f3max(l, pc, r)), KS[(row - 1) * ST + (c - 1)]);
        if (nv > cur) { MS[row * ST + c] = nv; ch = 1; }
        pc = nv;
    }
    return ch;
}

__device__ int relax_up(float* MS, const float* KS, int wy, int wx, int lane) {
    int ch = 0;
    const unsigned F = 0xffffffffu;
    const int r0 = (wy << 4) + 1, c0 = (wx << 5) + 1;
    float haloL = 0.0f, haloR = 0.0f;
    if (lane < 18) {
        haloL = MS[(r0 - 1 + lane) * ST + (c0 - 1)];
        haloR = MS[(r0 - 1 + lane) * ST + (c0 + 32)];
    }
    const int c = c0 + lane;
    float pc = MS[(r0 + 16) * ST + c];
    #pragma unroll 4
    for (int yy = 15; yy >= 0; yy--) {
        float l  = __shfl_up_sync(F, pc, 1);
        float r  = __shfl_down_sync(F, pc, 1);
        float hl = __shfl_sync(F, haloL, yy + 2);
        float hr = __shfl_sync(F, haloR, yy + 2);
        if (lane == 0)  l = hl;
        if (lane == 31) r = hr;
        const int row = r0 + yy;
        float cur = MS[row * ST + c];
        float nv  = fminf(fmaxf(cur, f3max(l, pc, r)), KS[(row - 1) * ST + (c - 1)]);
        if (nv > cur) { MS[row * ST + c] = nv; ch = 1; }
        pc = nv;
    }
    return ch;
}

__device__ int relax_right(float* MS, const float* KS, int wy, int wx, int lane) {
    int ch = 0;
    const unsigned F = 0xffffffffu;
    const int r0 = (wy << 4) + 1, c0 = (wx << 5) + 1;
    float haloTR = MS[(r0 - 1) * ST + (c0 - 1 + lane)];
    float haloBR = MS[(r0 + 16) * ST + (c0 - 1 + lane)];
    const int lr   = lane & 15;
    const int row  = r0 + lr;
    const bool act = (lane < 16);
    float pc = MS[row * ST + (c0 - 1)];
    #pragma unroll 4
    for (int xx = 0; xx < 32; xx++) {
        float u  = __shfl_up_sync(F, pc, 1);
        float d  = __shfl_down_sync(F, pc, 1);
        float ht = __shfl_sync(F, haloTR, xx);
        float hb = __shfl_sync(F, haloBR, xx);
        if (lr == 0)  u = ht;
        if (lr == 15) d = hb;
        const int c = c0 + xx;
        float cur = MS[row * ST + c];
        float nv  = fminf(fmaxf(cur, f3max(u, pc, d)), KS[(row - 1) * ST + (c - 1)]);
        if (act && nv > cur) { MS[row * ST + c] = nv; ch = 1; }
        pc = nv;
    }
    return ch;
}

__device__ int relax_left(float* MS, const float* KS, int wy, int wx, int lane) {
    int ch = 0;
    const unsigned F = 0xffffffffu;
    const int r0 = (wy << 4) + 1, c0 = (wx << 5) + 1;
    float haloTL = MS[(r0 - 1) * ST + (c0 + 1 + lane)];
    float haloBL = MS[(r0 + 16) * ST + (c0 + 1 + lane)];
    const int lr   = lane & 15;
    const int row  = r0 + lr;
    const bool act = (lane < 16);
    float pc = MS[row * ST + (c0 + 32)];
    #pragma unroll 4
    for (int xx = 31; xx >= 0; xx--) {
        float u  = __shfl_up_sync(F, pc, 1);
        float d  = __shfl_down_sync(F, pc, 1);
        float ht = __shfl_sync(F, haloTL, xx);
        float hb = __shfl_sync(F, haloBL, xx);
        if (lr == 0)  u = ht;
        if (lr == 15) d = hb;
        const int c = c0 + xx;
        float cur = MS[row * ST + c];
        float nv  = fminf(fmaxf(cur, f3max(u, pc, d)), KS[(row - 1) * ST + (c - 1)]);
        if (act && nv > cur) { MS[row * ST + c] = nv; ch = 1; }
        pc = nv;
    }
    return ch;
}

// ---- reconstruct(m, mask): block-per-region, band-sequential GS cycles ----
__device__ void reconstruct(float* m, const float* mask, int nb, int& epoch,
                            float* MS, float* KS) {
    const int tid  = threadIdx.x;
    const int wid  = tid >> 5;
    const int lane = tid & 31;
    const int wy   = wid >> 2, wx = wid & 3;   // 8x4 subtile grid
    __shared__ int s_cyc[2][NSUB];
    __shared__ int s_need, s_regch;
    const float NEGINF = __int_as_float(0xff800000);

    bool first = true;
    for (int pass = 0; pass < MAX_PASSES; pass++) {
        epoch++;
        for (int r = blockIdx.x; r < NREG; r += nb) {
            const int b  = r >> 4, idx = r & 15;
            const int ry = idx >> 2, rx = idx & 3;
            if (!first) {
                if (tid == 0) s_need = 0;
                __syncthreads();
                if (tid < 9) {
                    if (tid == 4) {
                        if (((volatile int*)g_reg_trunc)[r] >= epoch - 1)
                            atomicOr(&s_need, 1 << 9);       // trunc self-wake
                    } else {
                        int dy = tid / 3 - 1, dx = tid % 3 - 1;
                        int ny = ry + dy, nx = rx + dx;
                        if ((unsigned)ny < 4u && (unsigned)nx < 4u)
                            if (((volatile int*)g_reg_epoch)[(b << 4) + (ny << 2) + nx] >= epoch - 1)
                                atomicOr(&s_need, 1 << tid); // directional wake
                    }
                }
                __syncthreads();
                if (!s_need) continue;
            }
            const int need = first ? -1 : s_need;
            const size_t base = ((size_t)b) << 18;
            const int gy0 = ry * RS, gx0 = rx * RS;

            // load marker region + 1-px halo (out-of-image -> -inf)
            for (int i = tid; i < 130 * 130; i += THREADS) {
                int yy = i / 130, xx = i - yy * 130;
                int gy = gy0 + yy - 1, gx = gx0 + xx - 1;
                float v = NEGINF;
                if ((unsigned)gy < 512u && (unsigned)gx < 512u)
                    v = __ldcg(m + base + ((size_t)gy << 9) + gx);
                MS[yy * ST + xx] = v;
            }
            // load mask (interior)
            for (int i = tid; i < 128 * 128; i += THREADS) {
                int yy = i >> 7, xx = i & 127;
                KS[yy * ST + xx] = __ldcg(mask + base + ((size_t)(gy0 + yy) << 9) + (gx0 + xx));
            }
            if (tid == 0) s_regch = 0;
            __syncthreads();

            // initial dirty set from wake bits
            int dirty0;
            if (first || (need & (1 << 9))) {
                dirty0 = 1;
            } else {
                dirty0 = 0;
                #pragma unroll
                for (int k = 0; k < 9; k++) {
                    if (k == 4 || !(need & (1 << k))) continue;
                    int dy = k / 3 - 1, dx = k % 3 - 1;
                    int ty = (dy < 0) ? (wy == 0) : (dy > 0) ? (wy == 7) : 1;
                    int tx = (dx < 0) ? (wx == 0) : (dx > 0) ? (wx == 3) : 1;
                    if (ty && tx) dirty0 = 1;
                }
            }

            // region fixpoint: band-sequential directional Gauss-Seidel cycles
            int capped = 1;
            for (int cyc = 0; cyc < MAX_CYCLES; cyc++) {
                const int p = cyc & 1, q = 1 - p;
                int dirty;
                if (cyc == 0) dirty = dirty0;
                else {
                    dirty = 0;
                    #pragma unroll
                    for (int dy = -1; dy <= 1; dy++)
                        #pragma unroll
                        for (int dx = -1; dx <= 1; dx++) {
                            int ny = wy + dy, nx = wx + dx;
                            if ((unsigned)ny < 8u && (unsigned)nx < 4u)
                                dirty |= s_cyc[q][(ny << 2) + nx];
                        }
                }
                if (lane == 0) s_cyc[p][wid] = 0;
                __syncthreads();

                int chTot = 0;
                // DOWN: row-bands top -> bottom (fresh top halos)
                for (int band = 0; band < 8; band++) {
                    if (wy == band && dirty)
                        chTot |= __any_sync(0xffffffffu, relax_down(MS, KS, wy, wx, lane));
                    __syncthreads();
                }
                // UP: row-bands bottom -> top
                for (int band = 7; band >= 0; band--) {
                    if (wy == band && dirty)
                        chTot |= __any_sync(0xffffffffu, relax_up(MS, KS, wy, wx, lane));
                    __syncthreads();
                }
                // RIGHT: col-bands left -> right
                for (int cb = 0; cb < 4; cb++) {
                    if (wx == cb && dirty)
                        chTot |= __any_sync(0xffffffffu, relax_right(MS, KS, wy, wx, lane));
                    __syncthreads();
                }
                // LEFT: col-bands right -> left
                for (int cb = 3; cb >= 0; cb--) {
                    if (wx == cb && dirty)
                        chTot |= __any_sync(0xffffffffu, relax_left(MS, KS, wy, wx, lane));
                    __syncthreads();
                }

                if (chTot && lane == 0) { s_cyc[p][wid] = 1; s_regch = 1; }
                __syncthreads();
                int any = 0;
                #pragma unroll
                for (int w = 0; w < NSUB; w++) any |= s_cyc[p][w];
                if (!any) { capped = 0; break; }
            }

            if (s_regch) {
                for (int i = tid; i < 128 * 128; i += THREADS) {
                    int yy = i >> 7, xx = i & 127;
                    __stcg(m + base + ((size_t)(gy0 + yy) << 9) + (gx0 + xx),
                           MS[(yy + 1) * ST + (xx + 1)]);
                }
                if (tid == 0) {
                    ((volatile int*)g_reg_epoch)[r] = epoch;
                    ((volatile int*)g_flag_arr)[epoch] = 1;
                }
            }
            if (capped && tid == 0) ((volatile int*)g_reg_trunc)[r] = epoch;
            __syncthreads();   // protect smem reuse for next region
        }
        grid_sync(nb);
        // flag index `epoch` written only before this barrier, never reused
        if (!((volatile int*)g_flag_arr)[epoch]) break;
        first = false;
    }
}

__global__ void __launch_bounds__(THREADS, 1)
mega(const float* __restrict__ x, const float* __restrict__ hh,
     const float* __restrict__ u, float* __restrict__ out,
     int nb, long long xh_off, int write_cc)
{
    extern __shared__ float dynsm[];
    float* MS = dynsm;
    float* KS = dynsm + MS_WORDS;
    const int lane = threadIdx.x & 31;
    const int gtid = blockIdx.x * THREADS + threadIdx.x;
    const int nt   = nb * THREADS;

    // reset per-launch state; marker = x - h[b]  (coalesced streams)
    for (int i = gtid; i < NFLAGS; i += nt) g_flag_arr[i] = 0;
    for (int i = gtid; i < NREG; i += nt) { g_reg_epoch[i] = 0; g_reg_trunc[i] = 0; }
    if (gtid < Bn) g_cc[gtid] = 0u;
    if (gtid == 0) { g_hasone = 0; g_haszero = 0; }
    for (int i = gtid; i < NPX; i += nt) {
        float hv = __ldg(hh + (i >> 18));
        __stcg(g_bufA + i, x[i] - hv);
    }
    grid_sync(nb);

    int epoch = 0;
    // xh = reconstruct(x - h, x)
    reconstruct(g_bufA, x, nb, epoch, MS, KS);

    // write xh to output; marker2 = xh - eps
    for (int i = gtid; i < NPX; i += nt) {
        float v = __ldcg(g_bufA + i);
        out[xh_off + i] = v;
        __stcg(g_bufB + i, v - 1e-5f);
    }
    grid_sync(nb);
    // rec2 = reconstruct(xh - eps, xh)
    reconstruct(g_bufB, g_bufA, nb, epoch, MS, KS);

    // Rmax = (xh - rec2 > 0); M = min(u, Rmax); global has-one/has-zero
    int one = 0, zero = 0;
    for (int i = gtid; i < NPX; i += nt) {
        float rec = __ldcg(g_bufB + i);
        float xh  = __ldcg(g_bufA + i);
        float rmx = ((xh - rec) > 0.0f) ? 1.0f : 0.0f;
        if (rmx != 0.0f) one = 1; else zero = 1;
        __stcg(g_bufB + i, rmx);
        __stcg(g_bufC + i, fminf(u[i], rmx));
    }
    if (__any_sync(0xffffffffu, one)  && lane == 0) atomicOr(&g_hasone, 1);
    if (__any_sync(0xffffffffu, zero) && lane == 0) atomicOr(&g_haszero, 1);
    grid_sync(nb);
    // R = reconstruct(M, Rmax)
    reconstruct(g_bufC, g_bufB, nb, epoch, MS, KS);

    // Detection = (u == R); CC[b] via ballot+popc (exact integer counts)
    __shared__ unsigned s_cnt[Bn];
    if (threadIdx.x < Bn) s_cnt[threadIdx.x] = 0u;
    __syncthreads();
    for (int i = gtid; i < NPX; i += nt) {
        unsigned mball = __ballot_sync(0xffffffffu, u[i] == __ldcg(g_bufC + i));
        if (lane == 0 && mball) atomicAdd(&s_cnt[i >> 18], (unsigned)__popc(mball));
    }
    __syncthreads();
    if (threadIdx.x < Bn && s_cnt[threadIdx.x])
        atomicAdd(&g_cc[threadIdx.x], s_cnt[threadIdx.x]);
    grid_sync(nb);

    if (write_cc && blockIdx.x == 0 && threadIdx.x < Bn) {
        int ho = ((volatile int*)&g_hasone)[0];
        int hz = ((volatile int*)&g_haszero)[0];
        float d  = (ho && hz) ? 1.0f : 0.0f;   // max(Rmax) - min(Rmax)
        float cc = (float)((volatile unsigned*)g_cc)[threadIdx.x];
        out[threadIdx.x] = fminf(cc, 100.0f * d * cc);
    }
}

extern "C" void kernel_launch(void* const* d_in, const int* in_sizes, int n_in,
                              void* d_out, int out_size) {
    const float* x = (const float*)d_in[0];
    const float* h = (const float*)d_in[1];
    const float* u = (const float*)d_in[2];
    float* out = (float*)d_out;

    int dev = 0;
    cudaGetDevice(&dev);
    int sms = 0;
    cudaDeviceGetAttribute(&sms, cudaDevAttrMultiProcessorCount, dev);
    if (sms <= 0) sms = 148;

    cudaFuncSetAttribute(mega, cudaFuncAttributeMaxDynamicSharedMemorySize, SMEM_BYTES);
    int occ = 0;
    cudaOccupancyMaxActiveBlocksPerMultiprocessor(&occ, mega, THREADS, SMEM_BYTES);
    if (occ < 1) occ = 1;
    int nb = sms * occ;   // all blocks resident -> software grid barrier safe

    long long xh_off = (long long)out_size - NPX;   // [CC_(16) | xh(N)]
    int write_cc = (xh_off >= Bn) ? 1 : 0;
    if (xh_off < 0) xh_off = 0;

    mega<<<nb, THREADS, SMEM_BYTES>>>(x, h, u, out, nb, xh_off, write_cc);
}

// round 14
// speedup vs baseline: 1.9620x; 1.9620x over previous
#include <cuda_runtime.h>
#include <cstdint>

#define Bn 16
#define IMG (512*512)           // 2^18
#define NPX (Bn*IMG)            // 4194304
#define RS 128                  // region size
#define RPI 16                  // 4x4 regions per image
#define NREG (Bn*RPI)           // 256
#define THREADS 512
#define ST 131                  // smem row stride (odd -> conflict-free both ways)
#define MS_WORDS (130*ST)
#define KS_WORDS (128*ST)
#define SMEM_BYTES ((MS_WORDS + KS_WORDS)*4)   // ~135 KB
#define MAX_ITERS 128
#define MAX_PASSES 400
#define NFLAGS 2048

// ---- device globals (static scratch) ----
__device__ float g_bufA[NPX];          // xh
__device__ float g_bufB[NPX];          // rec2 -> Rmax
__device__ float g_bufC[NPX];          // M -> R
__device__ int   g_reg_epoch[NREG];
__device__ int   g_reg_trunc[NREG];
__device__ int   g_flag_arr[NFLAGS];
__device__ unsigned g_cc[Bn];
__device__ int g_hasone, g_haszero;
__device__ unsigned g_bar_count = 0;
__device__ volatile unsigned g_bar_gen = 0;

// ---- software grid barrier (all blocks resident: 1 block/SM via smem) ----
__device__ __forceinline__ void grid_sync(int nb) {
    __syncthreads();
    if (threadIdx.x == 0) {
        __threadfence();
        unsigned gen = g_bar_gen;
        unsigned t = atomicAdd(&g_bar_count, 1u);
        if (t == (unsigned)nb - 1u) {
            atomicExch(&g_bar_count, 0u);
            __threadfence();
            g_bar_gen = gen + 1u;
        } else {
            while (g_bar_gen == gen) { __nanosleep(64); }
        }
        __threadfence();
    }
    __syncthreads();
}

__device__ __forceinline__ float f3max(float a, float b, float c) {
    return fmaxf(fmaxf(a, b), c);
}

// ---- full-length directional sweeps over the whole 128x128 region ----
// Register-carried center chain (exact GS along the sweep direction);
// diagonal neighbors read from smem (may be one iteration stale -> monotone-
// safe). No intra-sweep synchronization. Return PER-LANE changed flag.

// DOWN: slab = 32 columns; lane = column; 128 steps top->bottom.
__device__ int relax_down_full(float* MS, const float* KS, int slab, int lane) {
    int ch = 0;
    const int c = (slab << 5) + lane + 1;
    float pc = MS[0 * ST + c];                  // top halo
    #pragma unroll 4
    for (int row = 1; row <= 128; row++) {
        float l = MS[(row - 1) * ST + c - 1];
        float r = MS[(row - 1) * ST + c + 1];
        float cur = MS[row * ST + c];
        float nv  = fminf(fmaxf(cur, f3max(l, pc, r)), KS[(row - 1) * ST + (c - 1)]);
        if (nv > cur) { MS[row * ST + c] = nv; ch = 1; }
        pc = nv;
    }
    return ch;
}

// UP: 128 steps bottom->top.
__device__ int relax_up_full(float* MS, const float* KS, int slab, int lane) {
    int ch = 0;
    const int c = (slab << 5) + lane + 1;
    float pc = MS[129 * ST + c];                // bottom halo
    #pragma unroll 4
    for (int row = 128; row >= 1; row--) {
        float l = MS[(row + 1) * ST + c - 1];
        float r = MS[(row + 1) * ST + c + 1];
        float cur = MS[row * ST + c];
        float nv  = fminf(fmaxf(cur, f3max(l, pc, r)), KS[(row - 1) * ST + (c - 1)]);
        if (nv > cur) { MS[row * ST + c] = nv; ch = 1; }
        pc = nv;
    }
    return ch;
}

// RIGHT: slab = 32 rows; lane = row; 128 steps left->right.
__device__ int relax_right_full(float* MS, const float* KS, int slab, int lane) {
    int ch = 0;
    const int rr = (slab << 5) + lane + 1;
    float pc = MS[rr * ST + 0];                 // left halo
    #pragma unroll 4
    for (int c = 1; c <= 128; c++) {
        float u = MS[(rr - 1) * ST + c - 1];
        float d = MS[(rr + 1) * ST + c - 1];
        float cur = MS[rr * ST + c];
        float nv  = fminf(fmaxf(cur, f3max(u, pc, d)), KS[(rr - 1) * ST + (c - 1)]);
        if (nv > cur) { MS[rr * ST + c] = nv; ch = 1; }
        pc = nv;
    }
    return ch;
}

// LEFT: 128 steps right->left.
__device__ int relax_left_full(float* MS, const float* KS, int slab, int lane) {
    int ch = 0;
    const int rr = (slab << 5) + lane + 1;
    float pc = MS[rr * ST + 129];               // right halo
    #pragma unroll 4
    for (int c = 128; c >= 1; c--) {
        float u = MS[(rr - 1) * ST + c + 1];
        float d = MS[(rr + 1) * ST + c + 1];
        float cur = MS[rr * ST + c];
        float nv  = fminf(fmaxf(cur, f3max(u, pc, d)), KS[(rr - 1) * ST + (c - 1)]);
        if (nv > cur) { MS[rr * ST + c] = nv; ch = 1; }
        pc = nv;
    }
    return ch;
}

// ---- reconstruct(m, mask): block-per-region, concurrent full-sweep fixpoint ----
__device__ void reconstruct(float* m, const float* mask, int nb, int& epoch,
                            float* MS, float* KS) {
    const int tid  = threadIdx.x;
    const int wid  = tid >> 5;
    const int lane = tid & 31;
    __shared__ int s_ch[2][16];
    __shared__ int s_need;
    const float NEGINF = __int_as_float(0xff800000);

    bool first = true;
    for (int pass = 0; pass < MAX_PASSES; pass++) {
        epoch++;
        for (int r = blockIdx.x; r < NREG; r += nb) {
            const int b  = r >> 4, idx = r & 15;
            const int ry = idx >> 2, rx = idx & 3;
            if (!first) {
                if (tid == 0) s_need = 0;
                __syncthreads();
                if (tid < 9) {
                    if (tid == 4) {
                        if (((volatile int*)g_reg_trunc)[r] >= epoch - 1) s_need = 1;
                    } else {
                        int dy = tid / 3 - 1, dx = tid % 3 - 1;
                        int ny = ry + dy, nx = rx + dx;
                        if ((unsigned)ny < 4u && (unsigned)nx < 4u)
                            if (((volatile int*)g_reg_epoch)[(b << 4) + (ny << 2) + nx] >= epoch - 1)
                                s_need = 1;
                    }
                }
                __syncthreads();
                if (!s_need) continue;
            }
            const size_t base = ((size_t)b) << 18;
            const int gy0 = ry * RS, gx0 = rx * RS;

            // load marker region + 1-px halo (out-of-image -> -inf)
            for (int i = tid; i < 130 * 130; i += THREADS) {
                int yy = i / 130, xx = i - yy * 130;
                int gy = gy0 + yy - 1, gx = gx0 + xx - 1;
                float v = NEGINF;
                if ((unsigned)gy < 512u && (unsigned)gx < 512u)
                    v = __ldcg(m + base + ((size_t)gy << 9) + gx);
                MS[yy * ST + xx] = v;
            }
            // load mask (interior)
            for (int i = tid; i < 128 * 128; i += THREADS) {
                int yy = i >> 7, xx = i & 127;
                KS[yy * ST + xx] = __ldcg(mask + base + ((size_t)(gy0 + yy) << 9) + (gx0 + xx));
            }
            __syncthreads();

            // fixpoint: all 4 directions swept concurrently, full region length
            int anych = 0, capped = 1;
            for (int it = 0; it < MAX_ITERS; it++) {
                const int p = it & 1;
                int ch;
                if (wid < 4)       ch = relax_down_full (MS, KS, wid,      lane);
                else if (wid < 8)  ch = relax_up_full   (MS, KS, wid - 4,  lane);
                else if (wid < 12) ch = relax_right_full(MS, KS, wid - 8,  lane);
                else               ch = relax_left_full (MS, KS, wid - 12, lane);
                ch = __any_sync(0xffffffffu, ch);
                if (lane == 0) s_ch[p][wid] = ch;
                __syncthreads();
                int any = 0;
                #pragma unroll
                for (int w = 0; w < 16; w++) any |= s_ch[p][w];
                if (!any) { capped = 0; break; }
                anych = 1;
                // double-buffered s_ch: next iter writes the other slot
            }

            if (anych) {
                for (int i = tid; i < 128 * 128; i += THREADS) {
                    int yy = i >> 7, xx = i & 127;
                    __stcg(m + base + ((size_t)(gy0 + yy) << 9) + (gx0 + xx),
                           MS[(yy + 1) * ST + (xx + 1)]);
                }
                if (tid == 0) {
                    ((volatile int*)g_reg_epoch)[r] = epoch;
                    ((volatile int*)g_flag_arr)[epoch] = 1;
                }
            }
            if (capped && tid == 0) ((volatile int*)g_reg_trunc)[r] = epoch;
            __syncthreads();   // protect smem reuse for next region
        }
        grid_sync(nb);
        // flag index `epoch` written only before this barrier, never reused
        if (!((volatile int*)g_flag_arr)[epoch]) break;
        first = false;
    }
}

__global__ void __launch_bounds__(THREADS, 1)
mega(const float* __restrict__ x, const float* __restrict__ hh,
     const float* __restrict__ u, float* __restrict__ out,
     int nb, long long xh_off, int write_cc)
{
    extern __shared__ float dynsm[];
    float* MS = dynsm;
    float* KS = dynsm + MS_WORDS;
    const int lane = threadIdx.x & 31;
    const int gtid = blockIdx.x * THREADS + threadIdx.x;
    const int nt   = nb * THREADS;

    // reset per-launch state; marker = x - h[b]  (coalesced streams)
    for (int i = gtid; i < NFLAGS; i += nt) g_flag_arr[i] = 0;
    for (int i = gtid; i < NREG; i += nt) { g_reg_epoch[i] = 0; g_reg_trunc[i] = 0; }
    if (gtid < Bn) g_cc[gtid] = 0u;
    if (gtid == 0) { g_hasone = 0; g_haszero = 0; }
    for (int i = gtid; i < NPX; i += nt) {
        float hv = __ldg(hh + (i >> 18));
        __stcg(g_bufA + i, x[i] - hv);
    }
    grid_sync(nb);

    int epoch = 0;
    // xh = reconstruct(x - h, x)
    reconstruct(g_bufA, x, nb, epoch, MS, KS);

    // write xh to output; marker2 = xh - eps
    for (int i = gtid; i < NPX; i += nt) {
        float v = __ldcg(g_bufA + i);
        out[xh_off + i] = v;
        __stcg(g_bufB + i, v - 1e-5f);
    }
    grid_sync(nb);
    // rec2 = reconstruct(xh - eps, xh)
    reconstruct(g_bufB, g_bufA, nb, epoch, MS, KS);

    // Rmax = (xh - rec2 > 0); M = min(u, Rmax); global has-one/has-zero
    int one = 0, zero = 0;
    for (int i = gtid; i < NPX; i += nt) {
        float rec = __ldcg(g_bufB + i);
        float xh  = __ldcg(g_bufA + i);
        float rmx = ((xh - rec) > 0.0f) ? 1.0f : 0.0f;
        if (rmx != 0.0f) one = 1; else zero = 1;
        __stcg(g_bufB + i, rmx);
        __stcg(g_bufC + i, fminf(u[i], rmx));
    }
    if (__any_sync(0xffffffffu, one)  && lane == 0) atomicOr(&g_hasone, 1);
    if (__any_sync(0xffffffffu, zero) && lane == 0) atomicOr(&g_haszero, 1);
    grid_sync(nb);
    // R = reconstruct(M, Rmax)
    reconstruct(g_bufC, g_bufB, nb, epoch, MS, KS);

    // Detection = (u == R); CC[b] via ballot+popc (exact integer counts)
    __shared__ unsigned s_cnt[Bn];
    if (threadIdx.x < Bn) s_cnt[threadIdx.x] = 0u;
    __syncthreads();
    for (int i = gtid; i < NPX; i += nt) {
        unsigned mball = __ballot_sync(0xffffffffu, u[i] == __ldcg(g_bufC + i));
        if (lane == 0 && mball) atomicAdd(&s_cnt[i >> 18], (unsigned)__popc(mball));
    }
    __syncthreads();
    if (threadIdx.x < Bn && s_cnt[threadIdx.x])
        atomicAdd(&g_cc[threadIdx.x], s_cnt[threadIdx.x]);
    grid_sync(nb);

    if (write_cc && blockIdx.x == 0 && threadIdx.x < Bn) {
        int ho = ((volatile int*)&g_hasone)[0];
        int hz = ((volatile int*)&g_haszero)[0];
        float d  = (ho && hz) ? 1.0f : 0.0f;   // max(Rmax) - min(Rmax)
        float cc = (float)((volatile unsigned*)g_cc)[threadIdx.x];
        out[threadIdx.x] = fminf(cc, 100.0f * d * cc);
    }
}

extern "C" void kernel_launch(void* const* d_in, const int* in_sizes, int n_in,
                              void* d_out, int out_size) {
    const float* x = (const float*)d_in[0];
    const float* h = (const float*)d_in[1];
    const float* u = (const float*)d_in[2];
    float* out = (float*)d_out;

    int dev = 0;
    cudaGetDevice(&dev);
    int sms = 0;
    cudaDeviceGetAttribute(&sms, cudaDevAttrMultiProcessorCount, dev);
    if (sms <= 0) sms = 148;

    cudaFuncSetAttribute(mega, cudaFuncAttributeMaxDynamicSharedMemorySize, SMEM_BYTES);
    int occ = 0;
    cudaOccupancyMaxActiveBlocksPerMultiprocessor(&occ, mega, THREADS, SMEM_BYTES);
    if (occ < 1) occ = 1;
    int nb = sms * occ;   // all blocks resident -> software grid barrier safe

    long long xh_off = (long long)out_size - NPX;   // [CC_(16) | xh(N)]
    int write_cc = (xh_off >= Bn) ? 1 : 0;
    if (xh_off < 0) xh_off = 0;

    mega<<<nb, THREADS, SMEM_BYTES>>>(x, h, u, out, nb, xh_off, write_cc);
}

// round 15
// speedup vs baseline: 2.1359x; 1.0886x over previous
#include <cuda_runtime.h>
#include <cstdint>

#define Bn 16
#define IMG (512*512)           // 2^18
#define NPX (Bn*IMG)            // 4194304
#define RS 128                  // region size
#define RPI 16                  // 4x4 regions per image
#define NREG (Bn*RPI)           // 256
#define THREADS 512
#define ST 131                  // smem row stride (odd -> conflict-free both ways)
#define MS_WORDS (130*ST)
#define KS_WORDS (128*ST)
#define SMEM_BYTES ((MS_WORDS + KS_WORDS)*4)   // ~135 KB
#define MAX_ITERS 128
#define MAX_PASSES 400
#define NFLAGS 2048

// ---- device globals (static scratch) ----
__device__ float g_bufA[NPX];          // xh
__device__ float g_bufB[NPX];          // rec2 -> Rmax
__device__ float g_bufC[NPX];          // M -> R
__device__ int   g_reg_epoch[NREG];
__device__ int   g_reg_trunc[NREG];
__device__ int   g_flag_arr[NFLAGS];
__device__ unsigned g_cc[Bn];
__device__ int g_hasone, g_haszero;
__device__ unsigned g_bar_count = 0;
__device__ volatile unsigned g_bar_gen = 0;

// ---- software grid barrier (all blocks resident: 1 block/SM via smem) ----
__device__ __forceinline__ void grid_sync(int nb) {
    __syncthreads();
    if (threadIdx.x == 0) {
        __threadfence();
        unsigned gen = g_bar_gen;
        unsigned t = atomicAdd(&g_bar_count, 1u);
        if (t == (unsigned)nb - 1u) {
            atomicExch(&g_bar_count, 0u);
            __threadfence();
            g_bar_gen = gen + 1u;
        } else {
            while (g_bar_gen == gen) { __nanosleep(64); }
        }
        __threadfence();
    }
    __syncthreads();
}

__device__ __forceinline__ float f3max(float a, float b, float c) {
    return fmaxf(fmaxf(a, b), c);
}

// ---- full-length directional sweeps; lateral neighbors via shfl ----
// Center chain register-carried (exact GS along sweep direction); lanes 1..30
// take diagonals from warp neighbors' pc (exact); boundary lanes use halo
// register banks prefetched once per sweep (stale -> monotone-safe).
// 2 LDS per step (cur + mask). Return PER-LANE changed flag.

// DOWN: slab = 32 columns; lane = column; 128 steps top->bottom.
__device__ int relax_down_full(float* MS, const float* KS, int slab, int lane) {
    int ch = 0;
    const unsigned F = 0xffffffffu;
    const int c0 = (slab << 5) + 1;         // first interior col of slab
    const int c  = c0 + lane;
    float hL[4], hR[4];                      // rows j*32+lane, cols c0-1 / c0+32
    #pragma unroll
    for (int j = 0; j < 4; j++) {
        hL[j] = MS[(j * 32 + lane) * ST + (c0 - 1)];
        hR[j] = MS[(j * 32 + lane) * ST + (c0 + 32)];
    }
    float pc = MS[0 * ST + c];               // top halo
    #pragma unroll
    for (int j = 0; j < 4; j++) {
        const float hLj = hL[j], hRj = hR[j];
        #pragma unroll 8
        for (int s = 0; s < 32; s++) {
            const int row = j * 32 + s + 1;
            float l  = __shfl_up_sync(F, pc, 1);
            float r  = __shfl_down_sync(F, pc, 1);
            float hl = __shfl_sync(F, hLj, s);
            float hr = __shfl_sync(F, hRj, s);
            if (lane == 0)  l = hl;
            if (lane == 31) r = hr;
            float cur = MS[row * ST + c];
            float nv  = fminf(fmaxf(cur, f3max(l, pc, r)), KS[(row - 1) * ST + (c - 1)]);
            if (nv > cur) { MS[row * ST + c] = nv; ch = 1; }
            pc = nv;
        }
    }
    return ch;
}

// UP: 128 steps bottom->top; neighbor rows row+1 in 2..129.
__device__ int relax_up_full(float* MS, const float* KS, int slab, int lane) {
    int ch = 0;
    const unsigned F = 0xffffffffu;
    const int c0 = (slab << 5) + 1;
    const int c  = c0 + lane;
    float hL[4], hR[4];                      // rows j*32+lane+2
    #pragma unroll
    for (int j = 0; j < 4; j++) {
        hL[j] = MS[(j * 32 + lane + 2) * ST + (c0 - 1)];
        hR[j] = MS[(j * 32 + lane + 2) * ST + (c0 + 32)];
    }
    float pc = MS[129 * ST + c];             // bottom halo
    #pragma unroll
    for (int j = 3; j >= 0; j--) {
        const float hLj = hL[j], hRj = hR[j];
        #pragma unroll 8
        for (int s = 31; s >= 0; s--) {
            const int row = j * 32 + s + 1;  // 128..1
            float l  = __shfl_up_sync(F, pc, 1);
            float r  = __shfl_down_sync(F, pc, 1);
            float hl = __shfl_sync(F, hLj, s);
            float hr = __shfl_sync(F, hRj, s);
            if (lane == 0)  l = hl;
            if (lane == 31) r = hr;
            float cur = MS[row * ST + c];
            float nv  = fminf(fmaxf(cur, f3max(l, pc, r)), KS[(row - 1) * ST + (c - 1)]);
            if (nv > cur) { MS[row * ST + c] = nv; ch = 1; }
            pc = nv;
        }
    }
    return ch;
}

// RIGHT: slab = 32 rows; lane = row; 128 steps left->right.
__device__ int relax_right_full(float* MS, const float* KS, int slab, int lane) {
    int ch = 0;
    const unsigned F = 0xffffffffu;
    const int r0 = (slab << 5) + 1;          // first interior row of slab
    const int rr = r0 + lane;
    float hT[4], hB[4];                      // cols j*32+lane, rows r0-1 / r0+32
    #pragma unroll
    for (int j = 0; j < 4; j++) {
        hT[j] = MS[(r0 - 1) * ST + (j * 32 + lane)];
        hB[j] = MS[(r0 + 32) * ST + (j * 32 + lane)];
    }
    float pc = MS[rr * ST + 0];              // left halo
    #pragma unroll
    for (int j = 0; j < 4; j++) {
        const float hTj = hT[j], hBj = hB[j];
        #pragma unroll 8
        for (int s = 0; s < 32; s++) {
            const int cc = j * 32 + s + 1;
            float u  = __shfl_up_sync(F, pc, 1);
            float d  = __shfl_down_sync(F, pc, 1);
            float ht = __shfl_sync(F, hTj, s);
            float hb = __shfl_sync(F, hBj, s);
            if (lane == 0)  u = ht;
            if (lane == 31) d = hb;
            float cur = MS[rr * ST + cc];
            float nv  = fminf(fmaxf(cur, f3max(u, pc, d)), KS[(rr - 1) * ST + (cc - 1)]);
            if (nv > cur) { MS[rr * ST + cc] = nv; ch = 1; }
            pc = nv;
        }
    }
    return ch;
}

// LEFT: 128 steps right->left; neighbor cols c+1 in 2..129.
__device__ int relax_left_full(float* MS, const float* KS, int slab, int lane) {
    int ch = 0;
    const unsigned F = 0xffffffffu;
    const int r0 = (slab << 5) + 1;
    const int rr = r0 + lane;
    float hT[4], hB[4];                      // cols j*32+lane+2
    #pragma unroll
    for (int j = 0; j < 4; j++) {
        hT[j] = MS[(r0 - 1) * ST + (j * 32 + lane + 2)];
        hB[j] = MS[(r0 + 32) * ST + (j * 32 + lane + 2)];
    }
    float pc = MS[rr * ST + 129];            // right halo
    #pragma unroll
    for (int j = 3; j >= 0; j--) {
        const float hTj = hT[j], hBj = hB[j];
        #pragma unroll 8
        for (int s = 31; s >= 0; s--) {
            const int cc = j * 32 + s + 1;   // 128..1
            float u  = __shfl_up_sync(F, pc, 1);
            float d  = __shfl_down_sync(F, pc, 1);
            float ht = __shfl_sync(F, hTj, s);
            float hb = __shfl_sync(F, hBj, s);
            if (lane == 0)  u = ht;
            if (lane == 31) d = hb;
            float cur = MS[rr * ST + cc];
            float nv  = fminf(fmaxf(cur, f3max(u, pc, d)), KS[(rr - 1) * ST + (cc - 1)]);
            if (nv > cur) { MS[rr * ST + cc] = nv; ch = 1; }
            pc = nv;
        }
    }
    return ch;
}

// ---- reconstruct(m, mask): block-per-region, concurrent full-sweep fixpoint ----
__device__ void reconstruct(float* m, const float* mask, int nb, int& epoch,
                            float* MS, float* KS) {
    const int tid  = threadIdx.x;
    const int wid  = tid >> 5;
    const int lane = tid & 31;
    __shared__ int s_ch[2][16];
    __shared__ int s_need;
    const float NEGINF = __int_as_float(0xff800000);

    bool first = true;
    for (int pass = 0; pass < MAX_PASSES; pass++) {
        epoch++;
        for (int r = blockIdx.x; r < NREG; r += nb) {
            const int b  = r >> 4, idx = r & 15;
            const int ry = idx >> 2, rx = idx & 3;
            if (!first) {
                if (tid == 0) s_need = 0;
                __syncthreads();
                if (tid < 9) {
                    if (tid == 4) {
                        if (((volatile int*)g_reg_trunc)[r] >= epoch - 1) s_need = 1;
                    } else {
                        int dy = tid / 3 - 1, dx = tid % 3 - 1;
                        int ny = ry + dy, nx = rx + dx;
                        if ((unsigned)ny < 4u && (unsigned)nx < 4u)
                            if (((volatile int*)g_reg_epoch)[(b << 4) + (ny << 2) + nx] >= epoch - 1)
                                s_need = 1;
                    }
                }
                __syncthreads();
                if (!s_need) continue;
            }
            const size_t base = ((size_t)b) << 18;
            const int gy0 = ry * RS, gx0 = rx * RS;

            // load marker region + 1-px halo (out-of-image -> -inf)
            for (int i = tid; i < 130 * 130; i += THREADS) {
                int yy = i / 130, xx = i - yy * 130;
                int gy = gy0 + yy - 1, gx = gx0 + xx - 1;
                float v = NEGINF;
                if ((unsigned)gy < 512u && (unsigned)gx < 512u)
                    v = __ldcg(m + base + ((size_t)gy << 9) + gx);
                MS[yy * ST + xx] = v;
            }
            // load mask (interior)
            for (int i = tid; i < 128 * 128; i += THREADS) {
                int yy = i >> 7, xx = i & 127;
                KS[yy * ST + xx] = __ldcg(mask + base + ((size_t)(gy0 + yy) << 9) + (gx0 + xx));
            }
            __syncthreads();

            // fixpoint: all 4 directions swept concurrently, full region length
            int anych = 0, capped = 1;
            for (int it = 0; it < MAX_ITERS; it++) {
                const int p = it & 1;
                int ch;
                if (wid < 4)       ch = relax_down_full (MS, KS, wid,      lane);
                else if (wid < 8)  ch = relax_up_full   (MS, KS, wid - 4,  lane);
                else if (wid < 12) ch = relax_right_full(MS, KS, wid - 8,  lane);
                else               ch = relax_left_full (MS, KS, wid - 12, lane);
                ch = __any_sync(0xffffffffu, ch);
                if (lane == 0) s_ch[p][wid] = ch;
                __syncthreads();
                int any = 0;
                #pragma unroll
                for (int w = 0; w < 16; w++) any |= s_ch[p][w];
                if (!any) { capped = 0; break; }
                anych = 1;
            }

            if (anych) {
                for (int i = tid; i < 128 * 128; i += THREADS) {
                    int yy = i >> 7, xx = i & 127;
                    __stcg(m + base + ((size_t)(gy0 + yy) << 9) + (gx0 + xx),
                           MS[(yy + 1) * ST + (xx + 1)]);
                }
                if (tid == 0) {
                    ((volatile int*)g_reg_epoch)[r] = epoch;
                    ((volatile int*)g_flag_arr)[epoch] = 1;
                }
            }
            if (capped && tid == 0) ((volatile int*)g_reg_trunc)[r] = epoch;
            __syncthreads();   // protect smem reuse for next region
        }
        grid_sync(nb);
        // flag index `epoch` written only before this barrier, never reused
        if (!((volatile int*)g_flag_arr)[epoch]) break;
        first = false;
    }
}

__global__ void __launch_bounds__(THREADS, 1)
mega(const float* __restrict__ x, const float* __restrict__ hh,
     const float* __restrict__ u, float* __restrict__ out,
     int nb, long long xh_off, int write_cc)
{
    extern __shared__ float dynsm[];
    float* MS = dynsm;
    float* KS = dynsm + MS_WORDS;
    const int lane = threadIdx.x & 31;
    const int gtid = blockIdx.x * THREADS + threadIdx.x;
    const int nt   = nb * THREADS;

    // reset per-launch state; marker = x - h[b]  (coalesced streams)
    for (int i = gtid; i < NFLAGS; i += nt) g_flag_arr[i] = 0;
    for (int i = gtid; i < NREG; i += nt) { g_reg_epoch[i] = 0; g_reg_trunc[i] = 0; }
    if (gtid < Bn) g_cc[gtid] = 0u;
    if (gtid == 0) { g_hasone = 0; g_haszero = 0; }
    for (int i = gtid; i < NPX; i += nt) {
        float hv = __ldg(hh + (i >> 18));
        __stcg(g_bufA + i, x[i] - hv);
    }
    grid_sync(nb);

    int epoch = 0;
    // xh = reconstruct(x - h, x)
    reconstruct(g_bufA, x, nb, epoch, MS, KS);

    // write xh to output; marker2 = xh - eps
    for (int i = gtid; i < NPX; i += nt) {
        float v = __ldcg(g_bufA + i);
        out[xh_off + i] = v;
        __stcg(g_bufB + i, v - 1e-5f);
    }
    grid_sync(nb);
    // rec2 = reconstruct(xh - eps, xh)
    reconstruct(g_bufB, g_bufA, nb, epoch, MS, KS);

    // Rmax = (xh - rec2 > 0); M = min(u, Rmax); global has-one/has-zero
    int one = 0, zero = 0;
    for (int i = gtid; i < NPX; i += nt) {
        float rec = __ldcg(g_bufB + i);
        float xh  = __ldcg(g_bufA + i);
        float rmx = ((xh - rec) > 0.0f) ? 1.0f : 0.0f;
        if (rmx != 0.0f) one = 1; else zero = 1;
        __stcg(g_bufB + i, rmx);
        __stcg(g_bufC + i, fminf(u[i], rmx));
    }
    if (__any_sync(0xffffffffu, one)  && lane == 0) atomicOr(&g_hasone, 1);
    if (__any_sync(0xffffffffu, zero) && lane == 0) atomicOr(&g_haszero, 1);
    grid_sync(nb);
    // R = reconstruct(M, Rmax)
    reconstruct(g_bufC, g_bufB, nb, epoch, MS, KS);

    // Detection = (u == R); CC[b] via ballot+popc (exact integer counts)
    __shared__ unsigned s_cnt[Bn];
    if (threadIdx.x < Bn) s_cnt[threadIdx.x] = 0u;
    __syncthreads();
    for (int i = gtid; i < NPX; i += nt) {
        unsigned mball = __ballot_sync(0xffffffffu, u[i] == __ldcg(g_bufC + i));
        if (lane == 0 && mball) atomicAdd(&s_cnt[i >> 18], (unsigned)__popc(mball));
    }
    __syncthreads();
    if (threadIdx.x < Bn && s_cnt[threadIdx.x])
        atomicAdd(&g_cc[threadIdx.x], s_cnt[threadIdx.x]);
    grid_sync(nb);

    if (write_cc && blockIdx.x == 0 && threadIdx.x < Bn) {
        int ho = ((volatile int*)&g_hasone)[0];
        int hz = ((volatile int*)&g_haszero)[0];
        float d  = (ho && hz) ? 1.0f : 0.0f;   // max(Rmax) - min(Rmax)
        float cc = (float)((volatile unsigned*)g_cc)[threadIdx.x];
        out[threadIdx.x] = fminf(cc, 100.0f * d * cc);
    }
}

extern "C" void kernel_launch(void* const* d_in, const int* in_sizes, int n_in,
                              void* d_out, int out_size) {
    const float* x = (const float*)d_in[0];
    const float* h = (const float*)d_in[1];
    const float* u = (const float*)d_in[2];
    float* out = (float*)d_out;

    int dev = 0;
    cudaGetDevice(&dev);
    int sms = 0;
    cudaDeviceGetAttribute(&sms, cudaDevAttrMultiProcessorCount, dev);
    if (sms <= 0) sms = 148;

    cudaFuncSetAttribute(mega, cudaFuncAttributeMaxDynamicSharedMemorySize, SMEM_BYTES);
    int occ = 0;
    cudaOccupancyMaxActiveBlocksPerMultiprocessor(&occ, mega, THREADS, SMEM_BYTES);
    if (occ < 1) occ = 1;
    int nb = sms * occ;   // all blocks resident -> software grid barrier safe

    long long xh_off = (long long)out_size - NPX;   // [CC_(16) | xh(N)]
    int write_cc = (xh_off >= Bn) ? 1 : 0;
    if (xh_off < 0) xh_off = 0;

    mega<<<nb, THREADS, SMEM_BYTES>>>(x, h, u, out, nb, xh_off, write_cc);
}

// round 16
// speedup vs baseline: 2.1447x; 1.0041x over previous
#include <cuda_runtime.h>
#include <cstdint>

#define Bn 16
#define IMG (512*512)           // 2^18
#define NPX (Bn*IMG)            // 4194304
#define RS 128                  // region size
#define RPI 16                  // 4x4 regions per image
#define NREG (Bn*RPI)           // 256
#define THREADS 512
#define ST 131                  // smem row stride (odd -> conflict-free both ways)
#define MS_WORDS (130*ST)
#define KS_WORDS (128*ST)
#define SMEM_BYTES ((MS_WORDS + KS_WORDS)*4)   // ~135 KB
#define MAX_ITERS 128
#define MAX_PASSES 400
#define NFLAGS 2048

// ---- device globals (static scratch) ----
__device__ float g_bufA[NPX];          // xh
__device__ float g_bufB[NPX];          // rec2 -> Rmax
__device__ float g_bufC[NPX];          // M -> R
__device__ int   g_reg_epoch[NREG];
__device__ int   g_reg_trunc[NREG];
__device__ int   g_flag_arr[NFLAGS];
__device__ unsigned g_cc[Bn];
__device__ int g_hasone, g_haszero;
__device__ unsigned g_bar_count = 0;
__device__ volatile unsigned g_bar_gen = 0;

// ---- software grid barrier (all blocks resident: 1 block/SM via smem) ----
__device__ __forceinline__ void grid_sync(int nb) {
    __syncthreads();
    if (threadIdx.x == 0) {
        __threadfence();
        unsigned gen = g_bar_gen;
        unsigned t = atomicAdd(&g_bar_count, 1u);
        if (t == (unsigned)nb - 1u) {
            atomicExch(&g_bar_count, 0u);
            __threadfence();
            g_bar_gen = gen + 1u;
        } else {
            while (g_bar_gen == gen) { __nanosleep(64); }
        }
        __threadfence();
    }
    __syncthreads();
}

__device__ __forceinline__ float f3max(float a, float b, float c) {
    return fmaxf(fmaxf(a, b), c);
}

// ---- full-length directional sweeps; lateral neighbors via shfl ----
// Center chain register-carried (exact GS along sweep direction); lanes 1..30
// take diagonals from warp neighbors' pc (exact); boundary lanes use halo
// register banks prefetched once per sweep (stale -> monotone-safe).
// 2 LDS per step (cur + mask). Return PER-LANE changed flag.

// DOWN: slab = 32 columns; lane = column; 128 steps top->bottom.
__device__ int relax_down_full(float* MS, const float* KS, int slab, int lane) {
    int ch = 0;
    const unsigned F = 0xffffffffu;
    const int c0 = (slab << 5) + 1;         // first interior col of slab
    const int c  = c0 + lane;
    float hL[4], hR[4];                      // rows j*32+lane, cols c0-1 / c0+32
    #pragma unroll
    for (int j = 0; j < 4; j++) {
        hL[j] = MS[(j * 32 + lane) * ST + (c0 - 1)];
        hR[j] = MS[(j * 32 + lane) * ST + (c0 + 32)];
    }
    float pc = MS[0 * ST + c];               // top halo
    #pragma unroll
    for (int j = 0; j < 4; j++) {
        const float hLj = hL[j], hRj = hR[j];
        #pragma unroll 8
        for (int s = 0; s < 32; s++) {
            const int row = j * 32 + s + 1;
            float l  = __shfl_up_sync(F, pc, 1);
            float r  = __shfl_down_sync(F, pc, 1);
            float hl = __shfl_sync(F, hLj, s);
            float hr = __shfl_sync(F, hRj, s);
            if (lane == 0)  l = hl;
            if (lane == 31) r = hr;
            float cur = MS[row * ST + c];
            float nv  = fminf(fmaxf(cur, f3max(l, pc, r)), KS[(row - 1) * ST + (c - 1)]);
            if (nv > cur) { MS[row * ST + c] = nv; ch = 1; }
            pc = nv;
        }
    }
    return ch;
}

// UP: 128 steps bottom->top; neighbor rows row+1 in 2..129.
__device__ int relax_up_full(float* MS, const float* KS, int slab, int lane) {
    int ch = 0;
    const unsigned F = 0xffffffffu;
    const int c0 = (slab << 5) + 1;
    const int c  = c0 + lane;
    float hL[4], hR[4];                      // rows j*32+lane+2
    #pragma unroll
    for (int j = 0; j < 4; j++) {
        hL[j] = MS[(j * 32 + lane + 2) * ST + (c0 - 1)];
        hR[j] = MS[(j * 32 + lane + 2) * ST + (c0 + 32)];
    }
    float pc = MS[129 * ST + c];             // bottom halo
    #pragma unroll
    for (int j = 3; j >= 0; j--) {
        const float hLj = hL[j], hRj = hR[j];
        #pragma unroll 8
        for (int s = 31; s >= 0; s--) {
            const int row = j * 32 + s + 1;  // 128..1
            float l  = __shfl_up_sync(F, pc, 1);
            float r  = __shfl_down_sync(F, pc, 1);
            float hl = __shfl_sync(F, hLj, s);
            float hr = __shfl_sync(F, hRj, s);
            if (lane == 0)  l = hl;
            if (lane == 31) r = hr;
            float cur = MS[row * ST + c];
            float nv  = fminf(fmaxf(cur, f3max(l, pc, r)), KS[(row - 1) * ST + (c - 1)]);
            if (nv > cur) { MS[row * ST + c] = nv; ch = 1; }
            pc = nv;
        }
    }
    return ch;
}

// RIGHT: slab = 32 rows; lane = row; 128 steps left->right.
__device__ int relax_right_full(float* MS, const float* KS, int slab, int lane) {
    int ch = 0;
    const unsigned F = 0xffffffffu;
    const int r0 = (slab << 5) + 1;          // first interior row of slab
    const int rr = r0 + lane;
    float hT[4], hB[4];                      // cols j*32+lane, rows r0-1 / r0+32
    #pragma unroll
    for (int j = 0; j < 4; j++) {
        hT[j] = MS[(r0 - 1) * ST + (j * 32 + lane)];
        hB[j] = MS[(r0 + 32) * ST + (j * 32 + lane)];
    }
    float pc = MS[rr * ST + 0];              // left halo
    #pragma unroll
    for (int j = 0; j < 4; j++) {
        const float hTj = hT[j], hBj = hB[j];
        #pragma unroll 8
        for (int s = 0; s < 32; s++) {
            const int cc = j * 32 + s + 1;
            float u  = __shfl_up_sync(F, pc, 1);
            float d  = __shfl_down_sync(F, pc, 1);
            float ht = __shfl_sync(F, hTj, s);
            float hb = __shfl_sync(F, hBj, s);
            if (lane == 0)  u = ht;
            if (lane == 31) d = hb;
            float cur = MS[rr * ST + cc];
            float nv  = fminf(fmaxf(cur, f3max(u, pc, d)), KS[(rr - 1) * ST + (cc - 1)]);
            if (nv > cur) { MS[rr * ST + cc] = nv; ch = 1; }
            pc = nv;
        }
    }
    return ch;
}

// LEFT: 128 steps right->left; neighbor cols c+1 in 2..129.
__device__ int relax_left_full(float* MS, const float* KS, int slab, int lane) {
    int ch = 0;
    const unsigned F = 0xffffffffu;
    const int r0 = (slab << 5) + 1;
    const int rr = r0 + lane;
    float hT[4], hB[4];                      // cols j*32+lane+2
    #pragma unroll
    for (int j = 0; j < 4; j++) {
        hT[j] = MS[(r0 - 1) * ST + (j * 32 + lane + 2)];
        hB[j] = MS[(r0 + 32) * ST + (j * 32 + lane + 2)];
    }
    float pc = MS[rr * ST + 129];            // right halo
    #pragma unroll
    for (int j = 3; j >= 0; j--) {
        const float hTj = hT[j], hBj = hB[j];
        #pragma unroll 8
        for (int s = 31; s >= 0; s--) {
            const int cc = j * 32 + s + 1;   // 128..1
            float u  = __shfl_up_sync(F, pc, 1);
            float d  = __shfl_down_sync(F, pc, 1);
            float ht = __shfl_sync(F, hTj, s);
            float hb = __shfl_sync(F, hBj, s);
            if (lane == 0)  u = ht;
            if (lane == 31) d = hb;
            float cur = MS[rr * ST + cc];
            float nv  = fminf(fmaxf(cur, f3max(u, pc, d)), KS[(rr - 1) * ST + (cc - 1)]);
            if (nv > cur) { MS[rr * ST + cc] = nv; ch = 1; }
            pc = nv;
        }
    }
    return ch;
}

// ---- reconstruct(m, mask): block-per-region, concurrent full-sweep fixpoint ----
__device__ void reconstruct(float* m, const float* mask, int nb, int& epoch,
                            float* MS, float* KS) {
    const int tid  = threadIdx.x;
    const int wid  = tid >> 5;
    const int lane = tid & 31;
    __shared__ int s_ch[2][16];
    __shared__ int s_need;
    const float NEGINF = __int_as_float(0xff800000);

    bool first = true;
    for (int pass = 0; pass < MAX_PASSES; pass++) {
        epoch++;
        for (int r = blockIdx.x; r < NREG; r += nb) {
            const int b  = r >> 4, idx = r & 15;
            const int ry = idx >> 2, rx = idx & 3;
            if (!first) {
                if (tid == 0) s_need = 0;
                __syncthreads();
                if (tid < 9) {
                    if (tid == 4) {
                        if (((volatile int*)g_reg_trunc)[r] >= epoch - 1) s_need = 1;
                    } else {
                        int dy = tid / 3 - 1, dx = tid % 3 - 1;
                        int ny = ry + dy, nx = rx + dx;
                        if ((unsigned)ny < 4u && (unsigned)nx < 4u)
                            if (((volatile int*)g_reg_epoch)[(b << 4) + (ny << 2) + nx] >= epoch - 1)
                                s_need = 1;
                    }
                }
                __syncthreads();
                if (!s_need) continue;
            }
            const size_t base = ((size_t)b) << 18;
            const int gy0 = ry * RS, gx0 = rx * RS;

            // load marker region + 1-px halo (out-of-image -> -inf)
            for (int i = tid; i < 130 * 130; i += THREADS) {
                int yy = i / 130, xx = i - yy * 130;
                int gy = gy0 + yy - 1, gx = gx0 + xx - 1;
                float v = NEGINF;
                if ((unsigned)gy < 512u && (unsigned)gx < 512u)
                    v = __ldcg(m + base + ((size_t)gy << 9) + gx);
                MS[yy * ST + xx] = v;
            }
            // load mask (interior)
            for (int i = tid; i < 128 * 128; i += THREADS) {
                int yy = i >> 7, xx = i & 127;
                KS[yy * ST + xx] = __ldcg(mask + base + ((size_t)(gy0 + yy) << 9) + (gx0 + xx));
            }
            __syncthreads();

            // fixpoint: all 4 directions swept concurrently, full region length
            int anych = 0, capped = 1;
            for (int it = 0; it < MAX_ITERS; it++) {
                const int p = it & 1;
                int ch;
                if (wid < 4)       ch = relax_down_full (MS, KS, wid,      lane);
                else if (wid < 8)  ch = relax_up_full   (MS, KS, wid - 4,  lane);
                else if (wid < 12) ch = relax_right_full(MS, KS, wid - 8,  lane);
                else               ch = relax_left_full (MS, KS, wid - 12, lane);
                ch = __any_sync(0xffffffffu, ch);
                if (lane == 0) s_ch[p][wid] = ch;
                __syncthreads();
                int any = 0;
                #pragma unroll
                for (int w = 0; w < 16; w++) any |= s_ch[p][w];
                if (!any) { capped = 0; break; }
                anych = 1;
            }

            if (anych) {
                for (int i = tid; i < 128 * 128; i += THREADS) {
                    int yy = i >> 7, xx = i & 127;
                    __stcg(m + base + ((size_t)(gy0 + yy) << 9) + (gx0 + xx),
                           MS[(yy + 1) * ST + (xx + 1)]);
                }
                if (tid == 0) {
                    ((volatile int*)g_reg_epoch)[r] = epoch;
                    ((volatile int*)g_flag_arr)[epoch] = 1;
                }
            }
            if (capped && tid == 0) ((volatile int*)g_reg_trunc)[r] = epoch;
            __syncthreads();   // protect smem reuse for next region
        }
        grid_sync(nb);
        // flag index `epoch` written only before this barrier, never reused
        if (!((volatile int*)g_flag_arr)[epoch]) break;
        first = false;
    }
}

__global__ void __launch_bounds__(THREADS, 1)
mega(const float* __restrict__ x, const float* __restrict__ hh,
     const float* __restrict__ u, float* __restrict__ out,
     int nb, long long xh_off, int write_cc)
{
    extern __shared__ float dynsm[];
    float* MS = dynsm;
    float* KS = dynsm + MS_WORDS;
    const int lane = threadIdx.x & 31;
    const int gtid = blockIdx.x * THREADS + threadIdx.x;
    const int nt   = nb * THREADS;

    // reset per-launch state; marker = x - h[b]  (coalesced streams)
    for (int i = gtid; i < NFLAGS; i += nt) g_flag_arr[i] = 0;
    for (int i = gtid; i < NREG; i += nt) { g_reg_epoch[i] = 0; g_reg_trunc[i] = 0; }
    if (gtid < Bn) g_cc[gtid] = 0u;
    if (gtid == 0) { g_hasone = 0; g_haszero = 0; }
    for (int i = gtid; i < NPX; i += nt) {
        float hv = __ldg(hh + (i >> 18));
        __stcg(g_bufA + i, x[i] - hv);
    }
    grid_sync(nb);

    int epoch = 0;
    // xh = reconstruct(x - h, x)
    reconstruct(g_bufA, x, nb, epoch, MS, KS);

    // write xh to output; marker2 = xh - eps
    for (int i = gtid; i < NPX; i += nt) {
        float v = __ldcg(g_bufA + i);
        out[xh_off + i] = v;
        __stcg(g_bufB + i, v - 1e-5f);
    }
    grid_sync(nb);
    // rec2 = reconstruct(xh - eps, xh)
    reconstruct(g_bufB, g_bufA, nb, epoch, MS, KS);

    // Rmax = (xh - rec2 > 0); M = min(u, Rmax); global has-one/has-zero
    int one = 0, zero = 0;
    for (int i = gtid; i < NPX; i += nt) {
        float rec = __ldcg(g_bufB + i);
        float xh  = __ldcg(g_bufA + i);
        float rmx = ((xh - rec) > 0.0f) ? 1.0f : 0.0f;
        if (rmx != 0.0f) one = 1; else zero = 1;
        __stcg(g_bufB + i, rmx);
        __stcg(g_bufC + i, fminf(u[i], rmx));
    }
    if (__any_sync(0xffffffffu, one)  && lane == 0) atomicOr(&g_hasone, 1);
    if (__any_sync(0xffffffffu, zero) && lane == 0) atomicOr(&g_haszero, 1);
    grid_sync(nb);
    // R = reconstruct(M, Rmax)
    reconstruct(g_bufC, g_bufB, nb, epoch, MS, KS);

    // Detection = (u == R); CC[b] via ballot+popc (exact integer counts)
    __shared__ unsigned s_cnt[Bn];
    if (threadIdx.x < Bn) s_cnt[threadIdx.x] = 0u;
    __syncthreads();
    for (int i = gtid; i < NPX; i += nt) {
        unsigned mball = __ballot_sync(0xffffffffu, u[i] == __ldcg(g_bufC + i));
        if (lane == 0 && mball) atomicAdd(&s_cnt[i >> 18], (unsigned)__popc(mball));
    }
    __syncthreads();
    if (threadIdx.x < Bn && s_cnt[threadIdx.x])
        atomicAdd(&g_cc[threadIdx.x], s_cnt[threadIdx.x]);
    grid_sync(nb);

    if (write_cc && blockIdx.x == 0 && threadIdx.x < Bn) {
        int ho = ((volatile int*)&g_hasone)[0];
        int hz = ((volatile int*)&g_haszero)[0];
        float d  = (ho && hz) ? 1.0f : 0.0f;   // max(Rmax) - min(Rmax)
        float cc = (float)((volatile unsigned*)g_cc)[threadIdx.x];
        out[threadIdx.x] = fminf(cc, 100.0f * d * cc);
    }
}

extern "C" void kernel_launch(void* const* d_in, const int* in_sizes, int n_in,
                              void* d_out, int out_size) {
    const float* x = (const float*)d_in[0];
    const float* h = (const float*)d_in[1];
    const float* u = (const float*)d_in[2];
    float* out = (float*)d_out;

    int dev = 0;
    cudaGetDevice(&dev);
    int sms = 0;
    cudaDeviceGetAttribute(&sms, cudaDevAttrMultiProcessorCount, dev);
    if (sms <= 0) sms = 148;

    cudaFuncSetAttribute(mega, cudaFuncAttributeMaxDynamicSharedMemorySize, SMEM_BYTES);
    int occ = 0;
    cudaOccupancyMaxActiveBlocksPerMultiprocessor(&occ, mega, THREADS, SMEM_BYTES);
    if (occ < 1) occ = 1;
    int nb = sms * occ;   // all blocks resident -> software grid barrier safe

    long long xh_off = (long long)out_size - NPX;   // [CC_(16) | xh(N)]
    int write_cc = (xh_off >= Bn) ? 1 : 0;
    if (xh_off < 0) xh_off = 0;

    mega<<<nb, THREADS, SMEM_BYTES>>>(x, h, u, out, nb, xh_off, write_cc);
}